// round 3
// baseline (speedup 1.0000x reference)
#include <cuda_runtime.h>
#include <math.h>

#define H 128
#define W 128
#define HW 16384
#define BATCH 4
#define NF 64
#define TOPK 3

typedef unsigned long long ull;

// ---------------- packed fp32x2 helpers (FFMA2) -------------------------------
__device__ __forceinline__ ull pk2(float a, float b) {
    ull r; asm("mov.b64 %0,{%1,%2};" : "=l"(r) : "f"(a), "f"(b)); return r;
}
__device__ __forceinline__ void upk2(ull v, float& a, float& b) {
    asm("mov.b64 {%0,%1},%2;" : "=f"(a), "=f"(b) : "l"(v));
}
__device__ __forceinline__ void ffma2(ull& d, ull a, ull b) {
    asm("fma.rn.f32x2 %0,%1,%2,%0;" : "+l"(d) : "l"(a), "l"(b));
}

// ---------------- device global scratch (allocation-free rule) ----------------
static __device__ float g_sup [TOPK*BATCH*HW];
static __device__ float g_ref [TOPK*BATCH*NF*HW];
static __device__ float g_off [TOPK*BATCH*18*HW];
static __device__ float g_mod [TOPK*BATCH*9*HW];
static __device__ float g_att [BATCH*NF*HW];
static __device__ float g_xA  [BATCH*NF*HW];
static __device__ float g_xB  [BATCH*NF*HW];
static __device__ float g_tmp [BATCH*NF*HW];
static __device__ float g_wom [TOPK*128*9*32];
static __device__ float g_wreg[TOPK*64*9*64];
static __device__ float g_wfuse[128*9*64];
static __device__ float g_wrb1[8*64*9*64];
static __device__ float g_wrb2[8*64*9*64];

// ---------------- weight transposes: w[O][C][9] -> [set][C][9][OP] -----------
__global__ void wt_generic(const float* __restrict__ src, float* __restrict__ dst,
                           int O, int C, int OP, int total) {
    int idx = blockIdx.x * blockDim.x + threadIdx.x;
    if (idx >= total) return;
    int per = C * 9 * OP;
    int s = idx / per;
    int r = idx - s * per;
    int c = r / (9 * OP);
    int r2 = r - c * (9 * OP);
    int k = r2 / OP;
    int o = r2 - k * OP;
    dst[idx] = (o < O) ? src[((s * O + o) * C + c) * 9 + k] : 0.f;
}

// off_w[3][18][128][9] + mod_w[3][9][128][9] -> g_wom [3][128][9][32]
__global__ void wt_om(const float* __restrict__ offw, const float* __restrict__ modw) {
    int idx = blockIdx.x * blockDim.x + threadIdx.x;
    const int total = TOPK * 128 * 9 * 32;
    if (idx >= total) return;
    int i = idx / (128 * 9 * 32);
    int r = idx - i * (128 * 9 * 32);
    int c = r / (9 * 32);
    int r2 = r - c * (9 * 32);
    int k = r2 / 32;
    int o = r2 - k * 32;
    float v = 0.f;
    if (o < 18)      v = offw[((i * 18 + o) * 128 + c) * 9 + k];
    else if (o < 27) v = modw[((i * 9 + (o - 18)) * 128 + c) * 9 + k];
    g_wom[idx] = v;
}

// ---------------- bicubic 2x upsample of S -----------------------------------
__global__ void sup_kernel(const float* __restrict__ S) {
    int idx = blockIdx.x * blockDim.x + threadIdx.x;
    if (idx >= TOPK * BATCH * HW) return;
    int ib = idx / HW;
    int p = idx & (HW - 1);
    int oy = p >> 7, ox = p & 127;
    const float* s = S + ib * 64 * 64;
    const float wE0 = -0.03515625f, wE1 = 0.26171875f, wE2 = 0.87890625f, wE3 = -0.10546875f;
    float wy[4], wx[4];
    if (oy & 1) { wy[0] = wE3; wy[1] = wE2; wy[2] = wE1; wy[3] = wE0; }
    else        { wy[0] = wE0; wy[1] = wE1; wy[2] = wE2; wy[3] = wE3; }
    if (ox & 1) { wx[0] = wE3; wx[1] = wE2; wx[2] = wE1; wx[3] = wE0; }
    else        { wx[0] = wE0; wx[1] = wE1; wx[2] = wE2; wx[3] = wE3; }
    int iy0 = (int)floorf(0.5f * (float)oy - 0.25f) - 1;
    int ix0 = (int)floorf(0.5f * (float)ox - 0.25f) - 1;
    float acc = 0.f;
    #pragma unroll
    for (int jy = 0; jy < 4; ++jy) {
        int yy = min(max(iy0 + jy, 0), 63);
        float row = 0.f;
        #pragma unroll
        for (int jx = 0; jx < 4; ++jx) {
            int xx = min(max(ix0 + jx, 0), 63);
            row += wx[jx] * s[yy * 64 + xx];
        }
        acc += wy[jy] * row;
    }
    g_sup[idx] = acc;
}

// ---------------- ref = T * broadcast(S_up) ----------------------------------
__global__ void ref_kernel(const float* __restrict__ T) {
    int idx = blockIdx.x * blockDim.x + threadIdx.x;
    const int total = TOPK * BATCH * NF * HW / 4;
    if (idx >= total) return;
    int q = idx & 4095;
    int ibc = idx >> 12;
    int ib = ibc / NF;
    float4 t = ((const float4*)T)[idx];
    float4 s = ((const float4*)g_sup)[ib * 4096 + q];
    float4 r;
    r.x = t.x * s.x; r.y = t.y * s.y; r.z = t.z * s.z; r.w = t.w * s.w;
    ((float4*)g_ref)[idx] = r;
}

// ---------------- offset/modulator conv (Cin=128 concat, Cout 27->32) --------
__global__ void __launch_bounds__(256) convom_kernel(const float* __restrict__ x,
                                                     const float* __restrict__ off_b,
                                                     const float* __restrict__ mod_b) {
    __shared__ float patch[8][6][34];
    __shared__ float wsm[2304];
    int tid = threadIdx.x;
    int bx = blockIdx.x, by = blockIdx.y, z = blockIdx.z;
    int i = z >> 2, b = z & 3;
    const float* inA = x + b * NF * HW;
    const float* inB = g_ref + (i * BATCH + b) * NF * HW;
    const float* wT = g_wom + i * (128 * 9 * 32);
    int g = tid >> 5, col = tid & 31;
    ull acc[4][2];
    #pragma unroll
    for (int a = 0; a < 4; ++a) { acc[a][0] = 0ull; acc[a][1] = 0ull; }

    for (int chunk = 0; chunk < 16; ++chunk) {
        for (int idx = tid; idx < 8 * 6 * 34; idx += 256) {
            int c = idx / 204;
            int r = (idx / 34) % 6;
            int cl = idx % 34;
            int y = by * 4 + r - 1, xx = bx * 32 + cl - 1;
            int gc = chunk * 8 + c;
            float v = 0.f;
            if ((unsigned)y < 128u && (unsigned)xx < 128u) {
                const float* src = (gc < 64) ? (inA + gc * HW) : (inB + (gc - 64) * HW);
                v = src[y * 128 + xx];
            }
            patch[c][r][cl] = v;
        }
        for (int idx = tid; idx < 2304; idx += 256) wsm[idx] = wT[chunk * 2304 + idx];
        __syncthreads();
        #pragma unroll
        for (int c = 0; c < 8; ++c) {
            ull pv[6][3];
            #pragma unroll
            for (int r = 0; r < 6; ++r)
                #pragma unroll
                for (int q = 0; q < 3; ++q) {
                    float v = patch[c][r][col + q];
                    pv[r][q] = pk2(v, v);
                }
            #pragma unroll
            for (int k = 0; k < 9; ++k) {
                const int ky = k / 3, kx = k - ky * 3;
                ulonglong2 wv = *(const ulonglong2*)&wsm[(c * 9 + k) * 32 + (g << 2)];
                #pragma unroll
                for (int ry = 0; ry < 4; ++ry) {
                    ull iv2 = pv[ry + ky][kx];
                    ffma2(acc[ry][0], iv2, wv.x);
                    ffma2(acc[ry][1], iv2, wv.y);
                }
            }
        }
        __syncthreads();
    }
    int oc0 = g << 2;
    int x0 = bx * 32 + col;
    #pragma unroll
    for (int pj = 0; pj < 2; ++pj) {
        #pragma unroll
        for (int ry = 0; ry < 4; ++ry) {
            float v0, v1;
            upk2(acc[ry][pj], v0, v1);
            float vv[2] = {v0, v1};
            #pragma unroll
            for (int h = 0; h < 2; ++h) {
                int oc = oc0 + pj * 2 + h;
                if (oc < 18) {
                    float v = vv[h] + off_b[i * 18 + oc];
                    v = fminf(fmaxf(v, -32.f), 32.f);
                    g_off[((i * BATCH + b) * 18 + oc) * HW + (by * 4 + ry) * 128 + x0] = v;
                } else if (oc < 27) {
                    float t = vv[h] + mod_b[i * 9 + (oc - 18)];
                    g_mod[((i * BATCH + b) * 9 + (oc - 18)) * HW + (by * 4 + ry) * 128 + x0]
                        = 2.f / (1.f + expf(-t));
                }
            }
        }
    }
}

// ---------------- generic conv3x3 Cout=64 (FFMA2, hoisted patch regs) --------
__global__ void __launch_bounds__(256) conv64_kernel(const float* __restrict__ inA,
                                                     const float* __restrict__ inB,
                                                     int nChunks,
                                                     const float* __restrict__ wT,
                                                     const float* __restrict__ bias,
                                                     const float* __restrict__ resid,
                                                     float* __restrict__ out,
                                                     int doRelu) {
    __shared__ float patch[8][6][34];
    __shared__ float wsm[4608];
    int tid = threadIdx.x;
    int bx = blockIdx.x, by = blockIdx.y, b = blockIdx.z;
    const float* inAb = inA + b * NF * HW;
    const float* inBb = inB ? (inB + b * NF * HW) : (const float*)0;
    int g = tid >> 5, col = tid & 31;
    ull acc[4][4];
    #pragma unroll
    for (int a = 0; a < 4; ++a)
        #pragma unroll
        for (int o = 0; o < 4; ++o) acc[a][o] = 0ull;

    for (int chunk = 0; chunk < nChunks; ++chunk) {
        for (int idx = tid; idx < 1632; idx += 256) {
            int c = idx / 204;
            int r = (idx / 34) % 6;
            int cl = idx % 34;
            int y = by * 4 + r - 1, xx = bx * 32 + cl - 1;
            int gc = chunk * 8 + c;
            float v = 0.f;
            if ((unsigned)y < 128u && (unsigned)xx < 128u) {
                const float* s = (gc < 64) ? (inAb + gc * HW) : (inBb + (gc - 64) * HW);
                v = s[y * 128 + xx];
            }
            patch[c][r][cl] = v;
        }
        for (int idx = tid; idx < 4608; idx += 256) wsm[idx] = wT[chunk * 4608 + idx];
        __syncthreads();
        #pragma unroll
        for (int c = 0; c < 8; ++c) {
            ull pv[6][3];
            #pragma unroll
            for (int r = 0; r < 6; ++r)
                #pragma unroll
                for (int q = 0; q < 3; ++q) {
                    float v = patch[c][r][col + q];
                    pv[r][q] = pk2(v, v);
                }
            #pragma unroll
            for (int k = 0; k < 9; ++k) {
                const int ky = k / 3, kx = k - ky * 3;
                const ulonglong2* wp = (const ulonglong2*)&wsm[(c * 9 + k) * 64 + (g << 3)];
                ulonglong2 wa = wp[0];
                ulonglong2 wb = wp[1];
                #pragma unroll
                for (int ry = 0; ry < 4; ++ry) {
                    ull iv2 = pv[ry + ky][kx];
                    ffma2(acc[ry][0], iv2, wa.x);
                    ffma2(acc[ry][1], iv2, wa.y);
                    ffma2(acc[ry][2], iv2, wb.x);
                    ffma2(acc[ry][3], iv2, wb.y);
                }
            }
        }
        __syncthreads();
    }
    int oc0 = g << 3;
    int x0 = bx * 32 + col;
    #pragma unroll
    for (int pj = 0; pj < 4; ++pj) {
        #pragma unroll
        for (int ry = 0; ry < 4; ++ry) {
            float v0, v1;
            upk2(acc[ry][pj], v0, v1);
            float vv[2] = {v0, v1};
            #pragma unroll
            for (int h = 0; h < 2; ++h) {
                int oc = oc0 + pj * 2 + h;
                float v = vv[h] + bias[oc];
                if (doRelu) v = fmaxf(v, 0.f);
                int oidx = (b * NF + oc) * HW + (by * 4 + ry) * 128 + x0;
                if (resid) v += resid[oidx];
                out[oidx] = v;
            }
        }
    }
}

// ---------------- deformable conv, summed over i=0..2 ------------------------
__global__ void __launch_bounds__(256) deform_kernel(const float* __restrict__ reg_b) {
    extern __shared__ float sm[];
    float* samp = sm;                   // 64 x 128
    float* wsm  = sm + 8192;            // 64 x 64
    float* mw   = sm + 12288;           // 4 x 128
    int*   mi   = (int*)(sm + 12800);   // 4 x 128
    int tid = threadIdx.x;
    int bx = blockIdx.x, by = blockIdx.y, b = blockIdx.z;
    int g = tid >> 5, col = tid & 31;
    ull acc[4][4];
    #pragma unroll
    for (int a = 0; a < 4; ++a)
        #pragma unroll
        for (int o = 0; o < 4; ++o) acc[a][o] = 0ull;
    int p = tid & 127;
    int chalf = tid >> 7;

    for (int i = 0; i < TOPK; ++i) {
        const float* refb = g_ref + (i * BATCH + b) * NF * HW;
        const float* offb = g_off + (i * BATCH + b) * 18 * HW;
        const float* modb = g_mod + (i * BATCH + b) * 9 * HW;
        const float* wbase = g_wreg + i * (64 * 9 * 64);
        for (int kk = 0; kk < 9; ++kk) {
            if (tid < 128) {
                int ry = tid >> 5, cl = tid & 31;
                int y = by * 4 + ry, xx = bx * 32 + cl;
                int po = y * 128 + xx;
                float dy = offb[(2 * kk) * HW + po];
                float dx = offb[(2 * kk + 1) * HW + po];
                float m  = modb[kk * HW + po];
                float py = (float)(y + kk / 3 - 1) + dy;
                float px = (float)(xx + kk % 3 - 1) + dx;
                float fy = floorf(py), fx = floorf(px);
                float ty = py - fy, tx = px - fx;
                int iy0 = (int)fy, ix0 = (int)fx;
                int iy1 = iy0 + 1, ix1 = ix0 + 1;
                float vy0 = ((unsigned)iy0 < 128u) ? 1.f : 0.f;
                float vy1 = ((unsigned)iy1 < 128u) ? 1.f : 0.f;
                float vx0 = ((unsigned)ix0 < 128u) ? 1.f : 0.f;
                float vx1 = ((unsigned)ix1 < 128u) ? 1.f : 0.f;
                mw[tid]       = (1.f - ty) * (1.f - tx) * m * vy0 * vx0;
                mw[128 + tid] = (1.f - ty) * tx * m * vy0 * vx1;
                mw[256 + tid] = ty * (1.f - tx) * m * vy1 * vx0;
                mw[384 + tid] = ty * tx * m * vy1 * vx1;
                mi[tid]       = min(max(iy0, 0), 127);
                mi[128 + tid] = min(max(iy1, 0), 127);
                mi[256 + tid] = min(max(ix0, 0), 127);
                mi[384 + tid] = min(max(ix1, 0), 127);
            } else {
                for (int idx = tid - 128; idx < 4096; idx += 128) {
                    int c = idx >> 6, o = idx & 63;
                    wsm[idx] = wbase[(c * 9 + kk) * 64 + o];
                }
            }
            __syncthreads();
            {
                int r0 = mi[p] * 128, r1 = mi[128 + p] * 128;
                int c0 = mi[256 + p], c1 = mi[384 + p];
                float f00 = mw[p], f01 = mw[128 + p], f10 = mw[256 + p], f11 = mw[384 + p];
                const float* rbase = refb + chalf * 32 * HW;
                #pragma unroll 4
                for (int j = 0; j < 32; ++j) {
                    const float* rc = rbase + j * HW;
                    float v = f00 * rc[r0 + c0] + f01 * rc[r0 + c1] +
                              f10 * rc[r1 + c0] + f11 * rc[r1 + c1];
                    samp[(chalf * 32 + j) * 128 + p] = v;
                }
            }
            __syncthreads();
            #pragma unroll 4
            for (int c = 0; c < 64; ++c) {
                const ulonglong2* wp = (const ulonglong2*)(wsm + c * 64 + (g << 3));
                ulonglong2 wa = wp[0];
                ulonglong2 wb = wp[1];
                float sv0 = samp[c * 128 + col];
                float sv1 = samp[c * 128 + 32 + col];
                float sv2 = samp[c * 128 + 64 + col];
                float sv3 = samp[c * 128 + 96 + col];
                ull s0 = pk2(sv0, sv0), s1 = pk2(sv1, sv1);
                ull s2 = pk2(sv2, sv2), s3 = pk2(sv3, sv3);
                ffma2(acc[0][0], s0, wa.x); ffma2(acc[0][1], s0, wa.y);
                ffma2(acc[0][2], s0, wb.x); ffma2(acc[0][3], s0, wb.y);
                ffma2(acc[1][0], s1, wa.x); ffma2(acc[1][1], s1, wa.y);
                ffma2(acc[1][2], s1, wb.x); ffma2(acc[1][3], s1, wb.y);
                ffma2(acc[2][0], s2, wa.x); ffma2(acc[2][1], s2, wa.y);
                ffma2(acc[2][2], s2, wb.x); ffma2(acc[2][3], s2, wb.y);
                ffma2(acc[3][0], s3, wa.x); ffma2(acc[3][1], s3, wa.y);
                ffma2(acc[3][2], s3, wb.x); ffma2(acc[3][3], s3, wb.y);
            }
            __syncthreads();
        }
    }
    int oc0 = g << 3;
    int x0 = bx * 32 + col;
    #pragma unroll
    for (int pj = 0; pj < 4; ++pj) {
        #pragma unroll
        for (int ry = 0; ry < 4; ++ry) {
            float v0, v1;
            upk2(acc[ry][pj], v0, v1);
            float vv[2] = {v0, v1};
            #pragma unroll
            for (int h = 0; h < 2; ++h) {
                int oc = oc0 + pj * 2 + h;
                float bs = reg_b[oc] + reg_b[64 + oc] + reg_b[128 + oc];
                g_att[(b * NF + oc) * HW + (by * 4 + ry) * 128 + x0] = vv[h] + bs;
            }
        }
    }
}

// ---------------- host launcher ----------------------------------------------
extern "C" void kernel_launch(void* const* d_in, const int* in_sizes, int n_in,
                              void* d_out, int out_size) {
    (void)in_sizes; (void)n_in; (void)out_size;
    const float* x      = (const float*)d_in[0];
    const float* T      = (const float*)d_in[1];
    const float* S      = (const float*)d_in[2];
    const float* off_w  = (const float*)d_in[3];
    const float* off_b  = (const float*)d_in[4];
    const float* mod_w  = (const float*)d_in[5];
    const float* mod_b  = (const float*)d_in[6];
    const float* reg_w  = (const float*)d_in[7];
    const float* reg_b  = (const float*)d_in[8];
    const float* fuse_w = (const float*)d_in[9];
    const float* fuse_b = (const float*)d_in[10];
    const float* rb_w1  = (const float*)d_in[11];
    const float* rb_b1  = (const float*)d_in[12];
    const float* rb_w2  = (const float*)d_in[13];
    const float* rb_b2  = (const float*)d_in[14];
    float* out = (float*)d_out;

    cudaFuncSetAttribute(deform_kernel, cudaFuncAttributeMaxDynamicSharedMemorySize, 53248);

    float *wreg, *wfuse, *wrb1, *wrb2, *xA, *xB, *tmp, *att;
    cudaGetSymbolAddress((void**)&wreg,  g_wreg);
    cudaGetSymbolAddress((void**)&wfuse, g_wfuse);
    cudaGetSymbolAddress((void**)&wrb1,  g_wrb1);
    cudaGetSymbolAddress((void**)&wrb2,  g_wrb2);
    cudaGetSymbolAddress((void**)&xA,    g_xA);
    cudaGetSymbolAddress((void**)&xB,    g_xB);
    cudaGetSymbolAddress((void**)&tmp,   g_tmp);
    cudaGetSymbolAddress((void**)&att,   g_att);

    {
        int tot = TOPK * 128 * 9 * 32;
        wt_om<<<(tot + 255) / 256, 256>>>(off_w, mod_w);
    }
    {
        int tot = TOPK * 64 * 9 * 64;
        wt_generic<<<(tot + 255) / 256, 256>>>(reg_w, wreg, 64, 64, 64, tot);
    }
    {
        int tot = 128 * 9 * 64;
        wt_generic<<<(tot + 255) / 256, 256>>>(fuse_w, wfuse, 64, 128, 64, tot);
    }
    {
        int tot = 8 * 64 * 9 * 64;
        wt_generic<<<(tot + 255) / 256, 256>>>(rb_w1, wrb1, 64, 64, 64, tot);
        wt_generic<<<(tot + 255) / 256, 256>>>(rb_w2, wrb2, 64, 64, 64, tot);
    }

    sup_kernel<<<(TOPK * BATCH * HW + 255) / 256, 256>>>(S);
    ref_kernel<<<(TOPK * BATCH * NF * HW / 4 + 255) / 256, 256>>>(T);

    convom_kernel<<<dim3(4, 32, 12), 256>>>(x, off_b, mod_b);

    deform_kernel<<<dim3(4, 32, 4), 256, 53248>>>(reg_b);

    conv64_kernel<<<dim3(4, 32, 4), 256>>>(x, att, 16, wfuse, fuse_b, x, xA, 0);

    float* cur = xA;
    float* nxt = xB;
    for (int r = 0; r < 8; ++r) {
        conv64_kernel<<<dim3(4, 32, 4), 256>>>(cur, (const float*)0, 8,
                                               wrb1 + r * 36864, rb_b1 + r * 64,
                                               (const float*)0, tmp, 1);
        float* o = (r == 7) ? out : nxt;
        conv64_kernel<<<dim3(4, 32, 4), 256>>>(tmp, (const float*)0, 8,
                                               wrb2 + r * 36864, rb_b2 + r * 64,
                                               cur, o, 0);
        float* t2 = cur; cur = nxt; nxt = t2;
    }
}

// round 4
// speedup vs baseline: 1.0580x; 1.0580x over previous
#include <cuda_runtime.h>
#include <math.h>

#define H 128
#define W 128
#define HW 16384
#define BATCH 4
#define NF 64
#define TOPK 3

typedef unsigned long long ull;

__device__ __forceinline__ ull pk2(float a, float b) {
    ull r; asm("mov.b64 %0,{%1,%2};" : "=l"(r) : "f"(a), "f"(b)); return r;
}
__device__ __forceinline__ void upk2(ull v, float& a, float& b) {
    asm("mov.b64 {%0,%1},%2;" : "=f"(a), "=f"(b) : "l"(v));
}
__device__ __forceinline__ void ffma2(ull& d, ull a, ull b) {
    asm("fma.rn.f32x2 %0,%1,%2,%0;" : "+l"(d) : "l"(a), "l"(b));
}

// ---------------- device global scratch --------------------------------------
static __device__ float g_sup [TOPK*BATCH*HW];
static __device__ float g_ref [TOPK*BATCH*NF*HW];
static __device__ float g_off [TOPK*BATCH*18*HW];
static __device__ float g_mod [TOPK*BATCH*9*HW];
static __device__ float g_att [BATCH*NF*HW];
static __device__ float g_xA  [BATCH*NF*HW];
static __device__ float g_xB  [BATCH*NF*HW];
static __device__ float g_tmp [BATCH*NF*HW];
static __device__ float g_wom [TOPK*128*9*32];
static __device__ float g_wreg[TOPK*64*9*64];
static __device__ float g_wfuse[128*9*64];
static __device__ float g_wrb1[8*64*9*64];
static __device__ float g_wrb2[8*64*9*64];

// ---------------- weight transposes: w[O][C][9] -> [set][C][9][OP] -----------
__global__ void wt_generic(const float* __restrict__ src, float* __restrict__ dst,
                           int O, int C, int OP, int total) {
    int idx = blockIdx.x * blockDim.x + threadIdx.x;
    if (idx >= total) return;
    int per = C * 9 * OP;
    int s = idx / per;
    int r = idx - s * per;
    int c = r / (9 * OP);
    int r2 = r - c * (9 * OP);
    int k = r2 / OP;
    int o = r2 - k * OP;
    dst[idx] = (o < O) ? src[((s * O + o) * C + c) * 9 + k] : 0.f;
}

__global__ void wt_om(const float* __restrict__ offw, const float* __restrict__ modw) {
    int idx = blockIdx.x * blockDim.x + threadIdx.x;
    const int total = TOPK * 128 * 9 * 32;
    if (idx >= total) return;
    int i = idx / (128 * 9 * 32);
    int r = idx - i * (128 * 9 * 32);
    int c = r / (9 * 32);
    int r2 = r - c * (9 * 32);
    int k = r2 / 32;
    int o = r2 - k * 32;
    float v = 0.f;
    if (o < 18)      v = offw[((i * 18 + o) * 128 + c) * 9 + k];
    else if (o < 27) v = modw[((i * 9 + (o - 18)) * 128 + c) * 9 + k];
    g_wom[idx] = v;
}

// ---------------- bicubic 2x upsample of S -----------------------------------
__global__ void sup_kernel(const float* __restrict__ S) {
    int idx = blockIdx.x * blockDim.x + threadIdx.x;
    if (idx >= TOPK * BATCH * HW) return;
    int ib = idx / HW;
    int p = idx & (HW - 1);
    int oy = p >> 7, ox = p & 127;
    const float* s = S + ib * 64 * 64;
    const float wE0 = -0.03515625f, wE1 = 0.26171875f, wE2 = 0.87890625f, wE3 = -0.10546875f;
    float wy[4], wx[4];
    if (oy & 1) { wy[0] = wE3; wy[1] = wE2; wy[2] = wE1; wy[3] = wE0; }
    else        { wy[0] = wE0; wy[1] = wE1; wy[2] = wE2; wy[3] = wE3; }
    if (ox & 1) { wx[0] = wE3; wx[1] = wE2; wx[2] = wE1; wx[3] = wE0; }
    else        { wx[0] = wE0; wx[1] = wE1; wx[2] = wE2; wx[3] = wE3; }
    int iy0 = (int)floorf(0.5f * (float)oy - 0.25f) - 1;
    int ix0 = (int)floorf(0.5f * (float)ox - 0.25f) - 1;
    float acc = 0.f;
    #pragma unroll
    for (int jy = 0; jy < 4; ++jy) {
        int yy = min(max(iy0 + jy, 0), 63);
        float row = 0.f;
        #pragma unroll
        for (int jx = 0; jx < 4; ++jx) {
            int xx = min(max(ix0 + jx, 0), 63);
            row += wx[jx] * s[yy * 64 + xx];
        }
        acc += wy[jy] * row;
    }
    g_sup[idx] = acc;
}

// ---------------- ref = T * broadcast(S_up) ----------------------------------
__global__ void ref_kernel(const float* __restrict__ T) {
    int idx = blockIdx.x * blockDim.x + threadIdx.x;
    const int total = TOPK * BATCH * NF * HW / 4;
    if (idx >= total) return;
    int q = idx & 4095;
    int ibc = idx >> 12;
    int ib = ibc / NF;
    float4 t = ((const float4*)T)[idx];
    float4 s = ((const float4*)g_sup)[ib * 4096 + q];
    float4 r;
    r.x = t.x * s.x; r.y = t.y * s.y; r.z = t.z * s.z; r.w = t.w * s.w;
    ((float4*)g_ref)[idx] = r;
}

// ---------------- offset/modulator conv (Cin=128 concat, Cout 27->32) --------
__global__ void __launch_bounds__(256) convom_kernel(const float* __restrict__ x,
                                                     const float* __restrict__ off_b,
                                                     const float* __restrict__ mod_b) {
    __shared__ ull patch[1792];                 // [c][r][cl] = 8*6*34, broadcast pairs (+pad)
    __shared__ __align__(16) float wsm[2304];
    int tid = threadIdx.x;
    int bx = blockIdx.x, by = blockIdx.y, z = blockIdx.z;
    int i = z >> 2, b = z & 3;
    const float* inA = x + b * NF * HW;
    const float* inB = g_ref + (i * BATCH + b) * NF * HW;
    const float* wT = g_wom + i * (128 * 9 * 32);
    int g = tid >> 5, col = tid & 31;
    ull acc[4][2];
    #pragma unroll
    for (int a = 0; a < 4; ++a) { acc[a][0] = 0ull; acc[a][1] = 0ull; }

    // precompute fill descriptors (7 slots/thread)
    int fcp[7], fgo[7], fso[7]; bool fva[7];
    #pragma unroll
    for (int f = 0; f < 7; ++f) {
        int idx = tid + f * 256;
        int c = idx / 204;
        int rr = idx - c * 204;
        int r = rr / 34;
        int cl = rr - r * 34;
        int y = by * 4 + r - 1, xx = bx * 32 + cl - 1;
        fcp[f] = (c & 7) * HW;
        fgo[f] = y * 128 + xx;
        fso[f] = idx;
        fva[f] = (idx < 1632) && ((unsigned)y < 128u) && ((unsigned)xx < 128u);
    }

    for (int chunk = 0; chunk < 16; ++chunk) {
        const float* bp = (chunk < 8) ? (inA + chunk * 8 * HW)
                                      : (inB + (chunk - 8) * 8 * HW);
        #pragma unroll
        for (int f = 0; f < 7; ++f) {
            float v = fva[f] ? bp[fcp[f] + fgo[f]] : 0.f;
            patch[fso[f]] = pk2(v, v);
        }
        #pragma unroll
        for (int it = 0; it < 9; ++it) wsm[tid + it * 256] = wT[chunk * 2304 + tid + it * 256];
        __syncthreads();
        #pragma unroll
        for (int c = 0; c < 8; ++c) {
            #pragma unroll
            for (int k = 0; k < 9; ++k) {
                const int ky = k / 3, kx = k - ky * 3;
                ulonglong2 wv = *(const ulonglong2*)&wsm[(c * 9 + k) * 32 + (g << 2)];
                #pragma unroll
                for (int ry = 0; ry < 4; ++ry) {
                    ull iv2 = patch[(c * 6 + ry + ky) * 34 + col + kx];
                    ffma2(acc[ry][0], iv2, wv.x);
                    ffma2(acc[ry][1], iv2, wv.y);
                }
            }
        }
        __syncthreads();
    }
    int oc0 = g << 2;
    int x0 = bx * 32 + col;
    #pragma unroll
    for (int pj = 0; pj < 2; ++pj) {
        #pragma unroll
        for (int ry = 0; ry < 4; ++ry) {
            float v0, v1;
            upk2(acc[ry][pj], v0, v1);
            float vv[2] = {v0, v1};
            #pragma unroll
            for (int h = 0; h < 2; ++h) {
                int oc = oc0 + pj * 2 + h;
                if (oc < 18) {
                    float v = vv[h] + off_b[i * 18 + oc];
                    v = fminf(fmaxf(v, -32.f), 32.f);
                    g_off[((i * BATCH + b) * 18 + oc) * HW + (by * 4 + ry) * 128 + x0] = v;
                } else if (oc < 27) {
                    float t = vv[h] + mod_b[i * 9 + (oc - 18)];
                    g_mod[((i * BATCH + b) * 9 + (oc - 18)) * HW + (by * 4 + ry) * 128 + x0]
                        = 2.f / (1.f + expf(-t));
                }
            }
        }
    }
}

// ---------------- generic conv3x3 Cout=64 ------------------------------------
__global__ void __launch_bounds__(256) conv64_kernel(const float* __restrict__ inA,
                                                     const float* __restrict__ inB,
                                                     int nChunks, int kSplit,
                                                     const float* __restrict__ wT,
                                                     const float* __restrict__ bias,
                                                     const float* __restrict__ resid,
                                                     float* __restrict__ out,
                                                     int doRelu) {
    __shared__ ull patch[1792];                 // broadcast pairs (+pad)
    __shared__ __align__(16) float wsm[4608];
    int tid = threadIdx.x;
    int bx = blockIdx.x, by = blockIdx.y, b = blockIdx.z;
    const float* inAb = inA + b * NF * HW;
    const float* inBb = inB ? (inB + b * NF * HW) : (const float*)0;
    int g = tid >> 5, col = tid & 31;
    ull acc[4][4];
    #pragma unroll
    for (int a = 0; a < 4; ++a)
        #pragma unroll
        for (int o = 0; o < 4; ++o) acc[a][o] = 0ull;

    int fcp[7], fgo[7], fso[7]; bool fva[7];
    #pragma unroll
    for (int f = 0; f < 7; ++f) {
        int idx = tid + f * 256;
        int c = idx / 204;
        int rr = idx - c * 204;
        int r = rr / 34;
        int cl = rr - r * 34;
        int y = by * 4 + r - 1, xx = bx * 32 + cl - 1;
        fcp[f] = (c & 7) * HW;
        fgo[f] = y * 128 + xx;
        fso[f] = idx;
        fva[f] = (idx < 1632) && ((unsigned)y < 128u) && ((unsigned)xx < 128u);
    }

    for (int chunk = 0; chunk < nChunks; ++chunk) {
        const float* bp = (chunk < kSplit) ? (inAb + chunk * 8 * HW)
                                           : (inBb + (chunk - kSplit) * 8 * HW);
        #pragma unroll
        for (int f = 0; f < 7; ++f) {
            float v = fva[f] ? bp[fcp[f] + fgo[f]] : 0.f;
            patch[fso[f]] = pk2(v, v);
        }
        #pragma unroll
        for (int it = 0; it < 18; ++it) wsm[tid + it * 256] = wT[chunk * 4608 + tid + it * 256];
        __syncthreads();
        #pragma unroll
        for (int c = 0; c < 8; ++c) {
            #pragma unroll
            for (int k = 0; k < 9; ++k) {
                const int ky = k / 3, kx = k - ky * 3;
                const ulonglong2* wp = (const ulonglong2*)&wsm[(c * 9 + k) * 64 + (g << 3)];
                ulonglong2 wa = wp[0];
                ulonglong2 wb = wp[1];
                #pragma unroll
                for (int ry = 0; ry < 4; ++ry) {
                    ull iv2 = patch[(c * 6 + ry + ky) * 34 + col + kx];
                    ffma2(acc[ry][0], iv2, wa.x);
                    ffma2(acc[ry][1], iv2, wa.y);
                    ffma2(acc[ry][2], iv2, wb.x);
                    ffma2(acc[ry][3], iv2, wb.y);
                }
            }
        }
        __syncthreads();
    }
    int oc0 = g << 3;
    int x0 = bx * 32 + col;
    #pragma unroll
    for (int pj = 0; pj < 4; ++pj) {
        #pragma unroll
        for (int ry = 0; ry < 4; ++ry) {
            float v0, v1;
            upk2(acc[ry][pj], v0, v1);
            float vv[2] = {v0, v1};
            #pragma unroll
            for (int h = 0; h < 2; ++h) {
                int oc = oc0 + pj * 2 + h;
                float v = vv[h] + bias[oc];
                if (doRelu) v = fmaxf(v, 0.f);
                int oidx = (b * NF + oc) * HW + (by * 4 + ry) * 128 + x0;
                if (resid) v += resid[oidx];
                out[oidx] = v;
            }
        }
    }
}

// ---------------- deformable conv, summed over i=0..2 ------------------------
__global__ void __launch_bounds__(256) deform_kernel(const float* __restrict__ reg_b) {
    extern __shared__ char smraw[];
    ull*   samp = (ull*)smraw;                       // 64 x 128 broadcast pairs (64KB)
    float* wsm  = (float*)(smraw + 65536);           // 64 x 64 (16KB)
    float* mw   = (float*)(smraw + 65536 + 16384);   // 4 x 128
    int*   mi   = (int*)  (smraw + 65536 + 16384 + 2048);
    int tid = threadIdx.x;
    int bx = blockIdx.x, by = blockIdx.y, b = blockIdx.z;
    int g = tid >> 5, col = tid & 31;
    ull acc[4][4];
    #pragma unroll
    for (int a = 0; a < 4; ++a)
        #pragma unroll
        for (int o = 0; o < 4; ++o) acc[a][o] = 0ull;
    int p = tid & 127;
    int chalf = tid >> 7;

    for (int i = 0; i < TOPK; ++i) {
        const float* refb = g_ref + (i * BATCH + b) * NF * HW;
        const float* offb = g_off + (i * BATCH + b) * 18 * HW;
        const float* modb = g_mod + (i * BATCH + b) * 9 * HW;
        const float* wbase = g_wreg + i * (64 * 9 * 64);
        for (int kk = 0; kk < 9; ++kk) {
            if (tid < 128) {
                int ry = tid >> 5, cl = tid & 31;
                int y = by * 4 + ry, xx = bx * 32 + cl;
                int po = y * 128 + xx;
                float dy = offb[(2 * kk) * HW + po];
                float dx = offb[(2 * kk + 1) * HW + po];
                float m  = modb[kk * HW + po];
                float py = (float)(y + kk / 3 - 1) + dy;
                float px = (float)(xx + kk % 3 - 1) + dx;
                float fy = floorf(py), fx = floorf(px);
                float ty = py - fy, tx = px - fx;
                int iy0 = (int)fy, ix0 = (int)fx;
                int iy1 = iy0 + 1, ix1 = ix0 + 1;
                float vy0 = ((unsigned)iy0 < 128u) ? 1.f : 0.f;
                float vy1 = ((unsigned)iy1 < 128u) ? 1.f : 0.f;
                float vx0 = ((unsigned)ix0 < 128u) ? 1.f : 0.f;
                float vx1 = ((unsigned)ix1 < 128u) ? 1.f : 0.f;
                mw[tid]       = (1.f - ty) * (1.f - tx) * m * vy0 * vx0;
                mw[128 + tid] = (1.f - ty) * tx * m * vy0 * vx1;
                mw[256 + tid] = ty * (1.f - tx) * m * vy1 * vx0;
                mw[384 + tid] = ty * tx * m * vy1 * vx1;
                mi[tid]       = min(max(iy0, 0), 127);
                mi[128 + tid] = min(max(iy1, 0), 127);
                mi[256 + tid] = min(max(ix0, 0), 127);
                mi[384 + tid] = min(max(ix1, 0), 127);
            } else {
                for (int idx = tid - 128; idx < 4096; idx += 128) {
                    wsm[idx] = wbase[((idx >> 6) * 9 + kk) * 64 + (idx & 63)];
                }
            }
            __syncthreads();
            {
                int r0 = mi[p] * 128, r1 = mi[128 + p] * 128;
                int c0 = mi[256 + p], c1 = mi[384 + p];
                float f00 = mw[p], f01 = mw[128 + p], f10 = mw[256 + p], f11 = mw[384 + p];
                const float* rbase = refb + chalf * 32 * HW;
                #pragma unroll 4
                for (int j = 0; j < 32; ++j) {
                    const float* rc = rbase + j * HW;
                    float v = f00 * rc[r0 + c0] + f01 * rc[r0 + c1] +
                              f10 * rc[r1 + c0] + f11 * rc[r1 + c1];
                    samp[(chalf * 32 + j) * 128 + p] = pk2(v, v);
                }
            }
            __syncthreads();
            #pragma unroll 4
            for (int c = 0; c < 64; ++c) {
                const ulonglong2* wp = (const ulonglong2*)(wsm + c * 64 + (g << 3));
                ulonglong2 wa = wp[0];
                ulonglong2 wb = wp[1];
                ull s0 = samp[c * 128 + col];
                ull s1 = samp[c * 128 + 32 + col];
                ull s2 = samp[c * 128 + 64 + col];
                ull s3 = samp[c * 128 + 96 + col];
                ffma2(acc[0][0], s0, wa.x); ffma2(acc[0][1], s0, wa.y);
                ffma2(acc[0][2], s0, wb.x); ffma2(acc[0][3], s0, wb.y);
                ffma2(acc[1][0], s1, wa.x); ffma2(acc[1][1], s1, wa.y);
                ffma2(acc[1][2], s1, wb.x); ffma2(acc[1][3], s1, wb.y);
                ffma2(acc[2][0], s2, wa.x); ffma2(acc[2][1], s2, wa.y);
                ffma2(acc[2][2], s2, wb.x); ffma2(acc[2][3], s2, wb.y);
                ffma2(acc[3][0], s3, wa.x); ffma2(acc[3][1], s3, wa.y);
                ffma2(acc[3][2], s3, wb.x); ffma2(acc[3][3], s3, wb.y);
            }
            __syncthreads();
        }
    }
    int oc0 = g << 3;
    int x0 = bx * 32 + col;
    #pragma unroll
    for (int pj = 0; pj < 4; ++pj) {
        #pragma unroll
        for (int ry = 0; ry < 4; ++ry) {
            float v0, v1;
            upk2(acc[ry][pj], v0, v1);
            float vv[2] = {v0, v1};
            #pragma unroll
            for (int h = 0; h < 2; ++h) {
                int oc = oc0 + pj * 2 + h;
                float bs = reg_b[oc] + reg_b[64 + oc] + reg_b[128 + oc];
                g_att[(b * NF + oc) * HW + (by * 4 + ry) * 128 + x0] = vv[h] + bs;
            }
        }
    }
}

// ---------------- host launcher ----------------------------------------------
extern "C" void kernel_launch(void* const* d_in, const int* in_sizes, int n_in,
                              void* d_out, int out_size) {
    (void)in_sizes; (void)n_in; (void)out_size;
    const float* x      = (const float*)d_in[0];
    const float* T      = (const float*)d_in[1];
    const float* S      = (const float*)d_in[2];
    const float* off_w  = (const float*)d_in[3];
    const float* off_b  = (const float*)d_in[4];
    const float* mod_w  = (const float*)d_in[5];
    const float* mod_b  = (const float*)d_in[6];
    const float* reg_w  = (const float*)d_in[7];
    const float* reg_b  = (const float*)d_in[8];
    const float* fuse_w = (const float*)d_in[9];
    const float* fuse_b = (const float*)d_in[10];
    const float* rb_w1  = (const float*)d_in[11];
    const float* rb_b1  = (const float*)d_in[12];
    const float* rb_w2  = (const float*)d_in[13];
    const float* rb_b2  = (const float*)d_in[14];
    float* out = (float*)d_out;

    cudaFuncSetAttribute(deform_kernel, cudaFuncAttributeMaxDynamicSharedMemorySize, 86016);

    float *wreg, *wfuse, *wrb1, *wrb2, *xA, *xB, *tmp, *att;
    cudaGetSymbolAddress((void**)&wreg,  g_wreg);
    cudaGetSymbolAddress((void**)&wfuse, g_wfuse);
    cudaGetSymbolAddress((void**)&wrb1,  g_wrb1);
    cudaGetSymbolAddress((void**)&wrb2,  g_wrb2);
    cudaGetSymbolAddress((void**)&xA,    g_xA);
    cudaGetSymbolAddress((void**)&xB,    g_xB);
    cudaGetSymbolAddress((void**)&tmp,   g_tmp);
    cudaGetSymbolAddress((void**)&att,   g_att);

    {
        int tot = TOPK * 128 * 9 * 32;
        wt_om<<<(tot + 255) / 256, 256>>>(off_w, mod_w);
    }
    {
        int tot = TOPK * 64 * 9 * 64;
        wt_generic<<<(tot + 255) / 256, 256>>>(reg_w, wreg, 64, 64, 64, tot);
    }
    {
        int tot = 128 * 9 * 64;
        wt_generic<<<(tot + 255) / 256, 256>>>(fuse_w, wfuse, 64, 128, 64, tot);
    }
    {
        int tot = 8 * 64 * 9 * 64;
        wt_generic<<<(tot + 255) / 256, 256>>>(rb_w1, wrb1, 64, 64, 64, tot);
        wt_generic<<<(tot + 255) / 256, 256>>>(rb_w2, wrb2, 64, 64, 64, tot);
    }

    sup_kernel<<<(TOPK * BATCH * HW + 255) / 256, 256>>>(S);
    ref_kernel<<<(TOPK * BATCH * NF * HW / 4 + 255) / 256, 256>>>(T);

    convom_kernel<<<dim3(4, 32, 12), 256>>>(x, off_b, mod_b);

    deform_kernel<<<dim3(4, 32, 4), 256, 86016>>>(reg_b);

    conv64_kernel<<<dim3(4, 32, 4), 256>>>(x, att, 16, 8, wfuse, fuse_b, x, xA, 0);

    float* cur = xA;
    float* nxt = xB;
    for (int r = 0; r < 8; ++r) {
        conv64_kernel<<<dim3(4, 32, 4), 256>>>(cur, (const float*)0, 8, 8,
                                               wrb1 + r * 36864, rb_b1 + r * 64,
                                               (const float*)0, tmp, 1);
        float* o = (r == 7) ? out : nxt;
        conv64_kernel<<<dim3(4, 32, 4), 256>>>(tmp, (const float*)0, 8, 8,
                                               wrb2 + r * 36864, rb_b2 + r * 64,
                                               cur, o, 0);
        float* t2 = cur; cur = nxt; nxt = t2;
    }
}

// round 5
// speedup vs baseline: 1.2987x; 1.2275x over previous
#include <cuda_runtime.h>
#include <math.h>

#define H 128
#define W 128
#define HW 16384
#define BATCH 4
#define NF 64
#define TOPK 3

typedef unsigned long long ull;

__device__ __forceinline__ ull pk2(float a, float b) {
    ull r; asm("mov.b64 %0,{%1,%2};" : "=l"(r) : "f"(a), "f"(b)); return r;
}
__device__ __forceinline__ void upk2(ull v, float& a, float& b) {
    asm("mov.b64 {%0,%1},%2;" : "=f"(a), "=f"(b) : "l"(v));
}
__device__ __forceinline__ void ffma2(ull& d, ull a, ull b) {
    asm("fma.rn.f32x2 %0,%1,%2,%0;" : "+l"(d) : "l"(a), "l"(b));
}
__device__ __forceinline__ unsigned smaddr(const void* p) {
    return (unsigned)__cvta_generic_to_shared(p);
}
__device__ __forceinline__ void cp4(unsigned s, const void* g, int pred) {
    asm volatile("{\n\t.reg .pred p;\n\tsetp.ne.u32 p,%2,0;\n\t"
                 "@p cp.async.ca.shared.global [%0],[%1],4;\n\t}"
                 :: "r"(s), "l"(g), "r"(pred));
}
__device__ __forceinline__ void cp16(unsigned s, const void* g, int pred) {
    asm volatile("{\n\t.reg .pred p;\n\tsetp.ne.u32 p,%2,0;\n\t"
                 "@p cp.async.cg.shared.global [%0],[%1],16;\n\t}"
                 :: "r"(s), "l"(g), "r"(pred));
}
__device__ __forceinline__ void cp_commit() { asm volatile("cp.async.commit_group;"); }
template<int N> __device__ __forceinline__ void cp_wait() {
    asm volatile("cp.async.wait_group %0;" :: "n"(N));
}

// ---------------- device global scratch --------------------------------------
static __device__ float g_sup [TOPK*BATCH*HW];
static __device__ float g_ref [TOPK*BATCH*NF*HW];
static __device__ float g_off [TOPK*BATCH*18*HW];
static __device__ float g_mod [TOPK*BATCH*9*HW];
static __device__ float g_att [BATCH*NF*HW];
static __device__ float g_xA  [BATCH*NF*HW];
static __device__ float g_xB  [BATCH*NF*HW];
static __device__ float g_tmp [BATCH*NF*HW];
static __device__ float g_wom [TOPK*128*9*32];
static __device__ float g_wreg[TOPK*64*9*64];
static __device__ float g_wfuse[128*9*64];
static __device__ float g_wrb1[8*64*9*64];
static __device__ float g_wrb2[8*64*9*64];

// ---------------- weight transposes ------------------------------------------
__global__ void wt_generic(const float* __restrict__ src, float* __restrict__ dst,
                           int O, int C, int OP, int total) {
    int idx = blockIdx.x * blockDim.x + threadIdx.x;
    if (idx >= total) return;
    int per = C * 9 * OP;
    int s = idx / per;
    int r = idx - s * per;
    int c = r / (9 * OP);
    int r2 = r - c * (9 * OP);
    int k = r2 / OP;
    int o = r2 - k * OP;
    dst[idx] = (o < O) ? src[((s * O + o) * C + c) * 9 + k] : 0.f;
}

__global__ void wt_om(const float* __restrict__ offw, const float* __restrict__ modw) {
    int idx = blockIdx.x * blockDim.x + threadIdx.x;
    const int total = TOPK * 128 * 9 * 32;
    if (idx >= total) return;
    int i = idx / (128 * 9 * 32);
    int r = idx - i * (128 * 9 * 32);
    int c = r / (9 * 32);
    int r2 = r - c * (9 * 32);
    int k = r2 / 32;
    int o = r2 - k * 32;
    float v = 0.f;
    if (o < 18)      v = offw[((i * 18 + o) * 128 + c) * 9 + k];
    else if (o < 27) v = modw[((i * 9 + (o - 18)) * 128 + c) * 9 + k];
    g_wom[idx] = v;
}

// ---------------- bicubic 2x upsample ----------------------------------------
__global__ void sup_kernel(const float* __restrict__ S) {
    int idx = blockIdx.x * blockDim.x + threadIdx.x;
    if (idx >= TOPK * BATCH * HW) return;
    int ib = idx / HW;
    int p = idx & (HW - 1);
    int oy = p >> 7, ox = p & 127;
    const float* s = S + ib * 64 * 64;
    const float wE0 = -0.03515625f, wE1 = 0.26171875f, wE2 = 0.87890625f, wE3 = -0.10546875f;
    float wy[4], wx[4];
    if (oy & 1) { wy[0] = wE3; wy[1] = wE2; wy[2] = wE1; wy[3] = wE0; }
    else        { wy[0] = wE0; wy[1] = wE1; wy[2] = wE2; wy[3] = wE3; }
    if (ox & 1) { wx[0] = wE3; wx[1] = wE2; wx[2] = wE1; wx[3] = wE0; }
    else        { wx[0] = wE0; wx[1] = wE1; wx[2] = wE2; wx[3] = wE3; }
    int iy0 = (int)floorf(0.5f * (float)oy - 0.25f) - 1;
    int ix0 = (int)floorf(0.5f * (float)ox - 0.25f) - 1;
    float acc = 0.f;
    #pragma unroll
    for (int jy = 0; jy < 4; ++jy) {
        int yy = min(max(iy0 + jy, 0), 63);
        float row = 0.f;
        #pragma unroll
        for (int jx = 0; jx < 4; ++jx) {
            int xx = min(max(ix0 + jx, 0), 63);
            row += wx[jx] * s[yy * 64 + xx];
        }
        acc += wy[jy] * row;
    }
    g_sup[idx] = acc;
}

// ---------------- ref = T * broadcast(S_up) ----------------------------------
__global__ void ref_kernel(const float* __restrict__ T) {
    int idx = blockIdx.x * blockDim.x + threadIdx.x;
    const int total = TOPK * BATCH * NF * HW / 4;
    if (idx >= total) return;
    int q = idx & 4095;
    int ibc = idx >> 12;
    int ib = ibc / NF;
    float4 t = ((const float4*)T)[idx];
    float4 s = ((const float4*)g_sup)[ib * 4096 + q];
    float4 r;
    r.x = t.x * s.x; r.y = t.y * s.y; r.z = t.z * s.z; r.w = t.w * s.w;
    ((float4*)g_ref)[idx] = r;
}

// ---------------- offset/modulator conv (pipelined) --------------------------
__global__ void __launch_bounds__(256) convom_kernel(const float* __restrict__ x,
                                                     const float* __restrict__ off_b,
                                                     const float* __restrict__ mod_b) {
    __shared__ float patchB[2][1632];
    __shared__ __align__(16) float wsmB[2][2304];
    int tid = threadIdx.x;
    int bx = blockIdx.x, by = blockIdx.y, z = blockIdx.z;
    int i = z >> 2, b = z & 3;
    const float* inA = x + b * NF * HW;
    const float* inB = g_ref + (i * BATCH + b) * NF * HW;
    const float* wT = g_wom + i * (128 * 9 * 32);
    int g = tid >> 5, col = tid & 31;
    ull acc[4][2];
    #pragma unroll
    for (int a = 0; a < 4; ++a) { acc[a][0] = 0ull; acc[a][1] = 0ull; }

    int fgo[7], fso[7], fcp[7]; int fva[7];
    #pragma unroll
    for (int f = 0; f < 7; ++f) {
        int idx = tid + f * 256;
        int c = idx / 204;
        int rr = idx - c * 204;
        int r = rr / 34;
        int cl = rr - r * 34;
        int y = by * 4 + r - 1, xx = bx * 32 + cl - 1;
        fcp[f] = (c & 7) * HW;
        fgo[f] = y * 128 + xx;
        fso[f] = idx;
        fva[f] = (idx < 1632) && ((unsigned)y < 128u) && ((unsigned)xx < 128u);
    }

    // pre-zero both patch buffers (border slots stay zero forever)
    for (int idx = tid; idx < 1632; idx += 256) { patchB[0][idx] = 0.f; patchB[1][idx] = 0.f; }
    __syncthreads();

    // prologue: issue chunk 0
    {
        const float* bp = inA;
        #pragma unroll
        for (int f = 0; f < 7; ++f)
            cp4(smaddr(&patchB[0][0]) + fso[f] * 4, bp + fcp[f] + fgo[f], fva[f]);
        #pragma unroll
        for (int f = 0; f < 3; ++f) {
            int idx = tid + f * 256;
            cp16(smaddr(&wsmB[0][0]) + idx * 16, wT + idx * 4, (f < 2) || (tid < 64));
        }
        cp_commit();
    }

    for (int chunk = 0; chunk < 16; ++chunk) {
        int cur = chunk & 1;
        if (chunk + 1 < 16) {
            int nxt = cur ^ 1;
            int nc = chunk + 1;
            const float* bp = (nc < 8) ? (inA + nc * 8 * HW) : (inB + (nc - 8) * 8 * HW);
            #pragma unroll
            for (int f = 0; f < 7; ++f)
                cp4(smaddr(&patchB[nxt][0]) + fso[f] * 4, bp + fcp[f] + fgo[f], fva[f]);
            const float* wc = wT + nc * 2304;
            #pragma unroll
            for (int f = 0; f < 3; ++f) {
                int idx = tid + f * 256;
                cp16(smaddr(&wsmB[nxt][0]) + idx * 16, wc + idx * 4, (f < 2) || (tid < 64));
            }
            cp_commit();
            cp_wait<1>();
        } else {
            cp_wait<0>();
        }
        __syncthreads();
        const float* patch = patchB[cur];
        const float* wsm = wsmB[cur];
        #pragma unroll
        for (int c = 0; c < 8; ++c) {
            #pragma unroll
            for (int k = 0; k < 9; ++k) {
                const int ky = k / 3, kx = k - ky * 3;
                ulonglong2 wv = *(const ulonglong2*)&wsm[(c * 9 + k) * 32 + (g << 2)];
                #pragma unroll
                for (int ry = 0; ry < 4; ++ry) {
                    float iv = patch[(c * 6 + ry + ky) * 34 + col + kx];
                    ull iv2 = pk2(iv, iv);
                    ffma2(acc[ry][0], iv2, wv.x);
                    ffma2(acc[ry][1], iv2, wv.y);
                }
            }
        }
        __syncthreads();
    }
    int oc0 = g << 2;
    int x0 = bx * 32 + col;
    #pragma unroll
    for (int pj = 0; pj < 2; ++pj) {
        #pragma unroll
        for (int ry = 0; ry < 4; ++ry) {
            float v0, v1;
            upk2(acc[ry][pj], v0, v1);
            float vv[2] = {v0, v1};
            #pragma unroll
            for (int h = 0; h < 2; ++h) {
                int oc = oc0 + pj * 2 + h;
                if (oc < 18) {
                    float v = vv[h] + off_b[i * 18 + oc];
                    v = fminf(fmaxf(v, -32.f), 32.f);
                    g_off[((i * BATCH + b) * 18 + oc) * HW + (by * 4 + ry) * 128 + x0] = v;
                } else if (oc < 27) {
                    float t = vv[h] + mod_b[i * 9 + (oc - 18)];
                    g_mod[((i * BATCH + b) * 9 + (oc - 18)) * HW + (by * 4 + ry) * 128 + x0]
                        = 2.f / (1.f + expf(-t));
                }
            }
        }
    }
}

// ---------------- generic conv3x3 Cout=64 (pipelined) ------------------------
__global__ void __launch_bounds__(256) conv64_kernel(const float* __restrict__ inA,
                                                     const float* __restrict__ inB,
                                                     int nChunks, int kSplit,
                                                     const float* __restrict__ wT,
                                                     const float* __restrict__ bias,
                                                     const float* __restrict__ resid,
                                                     float* __restrict__ out,
                                                     int doRelu) {
    extern __shared__ __align__(16) float dynsm[];
    float* patchB0 = dynsm;              // 1632
    float* patchB1 = dynsm + 1632;       // 1632
    float* wsmB0   = dynsm + 3264;       // 4608
    float* wsmB1   = dynsm + 7872;       // 4608
    int tid = threadIdx.x;
    int bx = blockIdx.x, by = blockIdx.y, b = blockIdx.z;
    const float* inAb = inA + b * NF * HW;
    const float* inBb = inB ? (inB + b * NF * HW) : (const float*)0;
    int g = tid >> 5, col = tid & 31;
    ull acc[4][4];
    #pragma unroll
    for (int a = 0; a < 4; ++a)
        #pragma unroll
        for (int o = 0; o < 4; ++o) acc[a][o] = 0ull;

    int fgo[7], fso[7], fcp[7]; int fva[7];
    #pragma unroll
    for (int f = 0; f < 7; ++f) {
        int idx = tid + f * 256;
        int c = idx / 204;
        int rr = idx - c * 204;
        int r = rr / 34;
        int cl = rr - r * 34;
        int y = by * 4 + r - 1, xx = bx * 32 + cl - 1;
        fcp[f] = (c & 7) * HW;
        fgo[f] = y * 128 + xx;
        fso[f] = idx;
        fva[f] = (idx < 1632) && ((unsigned)y < 128u) && ((unsigned)xx < 128u);
    }

    for (int idx = tid; idx < 1632; idx += 256) { patchB0[idx] = 0.f; patchB1[idx] = 0.f; }
    __syncthreads();

    {
        const float* bp = (0 < kSplit) ? inAb : inBb;
        #pragma unroll
        for (int f = 0; f < 7; ++f)
            cp4(smaddr(patchB0) + fso[f] * 4, bp + fcp[f] + fgo[f], fva[f]);
        #pragma unroll
        for (int f = 0; f < 5; ++f) {
            int idx = tid + f * 256;
            cp16(smaddr(wsmB0) + idx * 16, wT + idx * 4, (f < 4) || (tid < 128));
        }
        cp_commit();
    }

    for (int chunk = 0; chunk < nChunks; ++chunk) {
        int cur = chunk & 1;
        if (chunk + 1 < nChunks) {
            int nc = chunk + 1;
            float* pb = (cur == 0) ? patchB1 : patchB0;
            float* wb = (cur == 0) ? wsmB1 : wsmB0;
            const float* bp = (nc < kSplit) ? (inAb + nc * 8 * HW)
                                            : (inBb + (nc - kSplit) * 8 * HW);
            #pragma unroll
            for (int f = 0; f < 7; ++f)
                cp4(smaddr(pb) + fso[f] * 4, bp + fcp[f] + fgo[f], fva[f]);
            const float* wc = wT + nc * 4608;
            #pragma unroll
            for (int f = 0; f < 5; ++f) {
                int idx = tid + f * 256;
                cp16(smaddr(wb) + idx * 16, wc + idx * 4, (f < 4) || (tid < 128));
            }
            cp_commit();
            cp_wait<1>();
        } else {
            cp_wait<0>();
        }
        __syncthreads();
        const float* patch = (cur == 0) ? patchB0 : patchB1;
        const float* wsm = (cur == 0) ? wsmB0 : wsmB1;
        #pragma unroll
        for (int c = 0; c < 8; ++c) {
            #pragma unroll
            for (int k = 0; k < 9; ++k) {
                const int ky = k / 3, kx = k - ky * 3;
                const ulonglong2* wp = (const ulonglong2*)&wsm[(c * 9 + k) * 64 + (g << 3)];
                ulonglong2 wa = wp[0];
                ulonglong2 wb2 = wp[1];
                #pragma unroll
                for (int ry = 0; ry < 4; ++ry) {
                    float iv = patch[(c * 6 + ry + ky) * 34 + col + kx];
                    ull iv2 = pk2(iv, iv);
                    ffma2(acc[ry][0], iv2, wa.x);
                    ffma2(acc[ry][1], iv2, wa.y);
                    ffma2(acc[ry][2], iv2, wb2.x);
                    ffma2(acc[ry][3], iv2, wb2.y);
                }
            }
        }
        __syncthreads();
    }
    int oc0 = g << 3;
    int x0 = bx * 32 + col;
    #pragma unroll
    for (int pj = 0; pj < 4; ++pj) {
        #pragma unroll
        for (int ry = 0; ry < 4; ++ry) {
            float v0, v1;
            upk2(acc[ry][pj], v0, v1);
            float vv[2] = {v0, v1};
            #pragma unroll
            for (int h = 0; h < 2; ++h) {
                int oc = oc0 + pj * 2 + h;
                float v = vv[h] + bias[oc];
                if (doRelu) v = fmaxf(v, 0.f);
                int oidx = (b * NF + oc) * HW + (by * 4 + ry) * 128 + x0;
                if (resid) v += resid[oidx];
                out[oidx] = v;
            }
        }
    }
}

// ---------------- deformable conv (R2 form) ----------------------------------
__global__ void __launch_bounds__(256) deform_kernel(const float* __restrict__ reg_b) {
    extern __shared__ float sm[];
    float* samp = sm;                   // 64 x 128
    float* wsm  = sm + 8192;            // 64 x 64
    float* mw   = sm + 12288;           // 4 x 128
    int*   mi   = (int*)(sm + 12800);   // 4 x 128
    int tid = threadIdx.x;
    int bx = blockIdx.x, by = blockIdx.y, b = blockIdx.z;
    int g = tid >> 5, col = tid & 31;
    ull acc[4][4];
    #pragma unroll
    for (int a = 0; a < 4; ++a)
        #pragma unroll
        for (int o = 0; o < 4; ++o) acc[a][o] = 0ull;
    int p = tid & 127;
    int chalf = tid >> 7;

    for (int i = 0; i < TOPK; ++i) {
        const float* refb = g_ref + (i * BATCH + b) * NF * HW;
        const float* offb = g_off + (i * BATCH + b) * 18 * HW;
        const float* modb = g_mod + (i * BATCH + b) * 9 * HW;
        const float* wbase = g_wreg + i * (64 * 9 * 64);
        for (int kk = 0; kk < 9; ++kk) {
            if (tid < 128) {
                int ry = tid >> 5, cl = tid & 31;
                int y = by * 4 + ry, xx = bx * 32 + cl;
                int po = y * 128 + xx;
                float dy = offb[(2 * kk) * HW + po];
                float dx = offb[(2 * kk + 1) * HW + po];
                float m  = modb[kk * HW + po];
                float py = (float)(y + kk / 3 - 1) + dy;
                float px = (float)(xx + kk % 3 - 1) + dx;
                float fy = floorf(py), fx = floorf(px);
                float ty = py - fy, tx = px - fx;
                int iy0 = (int)fy, ix0 = (int)fx;
                int iy1 = iy0 + 1, ix1 = ix0 + 1;
                float vy0 = ((unsigned)iy0 < 128u) ? 1.f : 0.f;
                float vy1 = ((unsigned)iy1 < 128u) ? 1.f : 0.f;
                float vx0 = ((unsigned)ix0 < 128u) ? 1.f : 0.f;
                float vx1 = ((unsigned)ix1 < 128u) ? 1.f : 0.f;
                mw[tid]       = (1.f - ty) * (1.f - tx) * m * vy0 * vx0;
                mw[128 + tid] = (1.f - ty) * tx * m * vy0 * vx1;
                mw[256 + tid] = ty * (1.f - tx) * m * vy1 * vx0;
                mw[384 + tid] = ty * tx * m * vy1 * vx1;
                mi[tid]       = min(max(iy0, 0), 127);
                mi[128 + tid] = min(max(iy1, 0), 127);
                mi[256 + tid] = min(max(ix0, 0), 127);
                mi[384 + tid] = min(max(ix1, 0), 127);
            } else {
                for (int idx = tid - 128; idx < 4096; idx += 128) {
                    wsm[idx] = wbase[((idx >> 6) * 9 + kk) * 64 + (idx & 63)];
                }
            }
            __syncthreads();
            {
                int r0 = mi[p] * 128, r1 = mi[128 + p] * 128;
                int c0 = mi[256 + p], c1 = mi[384 + p];
                float f00 = mw[p], f01 = mw[128 + p], f10 = mw[256 + p], f11 = mw[384 + p];
                const float* rbase = refb + chalf * 32 * HW;
                #pragma unroll 4
                for (int j = 0; j < 32; ++j) {
                    const float* rc = rbase + j * HW;
                    float v = f00 * rc[r0 + c0] + f01 * rc[r0 + c1] +
                              f10 * rc[r1 + c0] + f11 * rc[r1 + c1];
                    samp[(chalf * 32 + j) * 128 + p] = v;
                }
            }
            __syncthreads();
            #pragma unroll 4
            for (int c = 0; c < 64; ++c) {
                const ulonglong2* wp = (const ulonglong2*)(wsm + c * 64 + (g << 3));
                ulonglong2 wa = wp[0];
                ulonglong2 wb = wp[1];
                float sv0 = samp[c * 128 + col];
                float sv1 = samp[c * 128 + 32 + col];
                float sv2 = samp[c * 128 + 64 + col];
                float sv3 = samp[c * 128 + 96 + col];
                ull s0 = pk2(sv0, sv0), s1 = pk2(sv1, sv1);
                ull s2 = pk2(sv2, sv2), s3 = pk2(sv3, sv3);
                ffma2(acc[0][0], s0, wa.x); ffma2(acc[0][1], s0, wa.y);
                ffma2(acc[0][2], s0, wb.x); ffma2(acc[0][3], s0, wb.y);
                ffma2(acc[1][0], s1, wa.x); ffma2(acc[1][1], s1, wa.y);
                ffma2(acc[1][2], s1, wb.x); ffma2(acc[1][3], s1, wb.y);
                ffma2(acc[2][0], s2, wa.x); ffma2(acc[2][1], s2, wa.y);
                ffma2(acc[2][2], s2, wb.x); ffma2(acc[2][3], s2, wb.y);
                ffma2(acc[3][0], s3, wa.x); ffma2(acc[3][1], s3, wa.y);
                ffma2(acc[3][2], s3, wb.x); ffma2(acc[3][3], s3, wb.y);
            }
            __syncthreads();
        }
    }
    int oc0 = g << 3;
    int x0 = bx * 32 + col;
    #pragma unroll
    for (int pj = 0; pj < 4; ++pj) {
        #pragma unroll
        for (int ry = 0; ry < 4; ++ry) {
            float v0, v1;
            upk2(acc[ry][pj], v0, v1);
            float vv[2] = {v0, v1};
            #pragma unroll
            for (int h = 0; h < 2; ++h) {
                int oc = oc0 + pj * 2 + h;
                float bs = reg_b[oc] + reg_b[64 + oc] + reg_b[128 + oc];
                g_att[(b * NF + oc) * HW + (by * 4 + ry) * 128 + x0] = vv[h] + bs;
            }
        }
    }
}

// ---------------- host launcher ----------------------------------------------
extern "C" void kernel_launch(void* const* d_in, const int* in_sizes, int n_in,
                              void* d_out, int out_size) {
    (void)in_sizes; (void)n_in; (void)out_size;
    const float* x      = (const float*)d_in[0];
    const float* T      = (const float*)d_in[1];
    const float* S      = (const float*)d_in[2];
    const float* off_w  = (const float*)d_in[3];
    const float* off_b  = (const float*)d_in[4];
    const float* mod_w  = (const float*)d_in[5];
    const float* mod_b  = (const float*)d_in[6];
    const float* reg_w  = (const float*)d_in[7];
    const float* reg_b  = (const float*)d_in[8];
    const float* fuse_w = (const float*)d_in[9];
    const float* fuse_b = (const float*)d_in[10];
    const float* rb_w1  = (const float*)d_in[11];
    const float* rb_b1  = (const float*)d_in[12];
    const float* rb_w2  = (const float*)d_in[13];
    const float* rb_b2  = (const float*)d_in[14];
    float* out = (float*)d_out;

    const int CONV64_SMEM = (2 * 1632 + 2 * 4608) * 4;  // 49920 B
    cudaFuncSetAttribute(conv64_kernel, cudaFuncAttributeMaxDynamicSharedMemorySize, CONV64_SMEM);
    cudaFuncSetAttribute(deform_kernel, cudaFuncAttributeMaxDynamicSharedMemorySize, 53248);

    float *wreg, *wfuse, *wrb1, *wrb2, *xA, *xB, *tmp, *att;
    cudaGetSymbolAddress((void**)&wreg,  g_wreg);
    cudaGetSymbolAddress((void**)&wfuse, g_wfuse);
    cudaGetSymbolAddress((void**)&wrb1,  g_wrb1);
    cudaGetSymbolAddress((void**)&wrb2,  g_wrb2);
    cudaGetSymbolAddress((void**)&xA,    g_xA);
    cudaGetSymbolAddress((void**)&xB,    g_xB);
    cudaGetSymbolAddress((void**)&tmp,   g_tmp);
    cudaGetSymbolAddress((void**)&att,   g_att);

    {
        int tot = TOPK * 128 * 9 * 32;
        wt_om<<<(tot + 255) / 256, 256>>>(off_w, mod_w);
    }
    {
        int tot = TOPK * 64 * 9 * 64;
        wt_generic<<<(tot + 255) / 256, 256>>>(reg_w, wreg, 64, 64, 64, tot);
    }
    {
        int tot = 128 * 9 * 64;
        wt_generic<<<(tot + 255) / 256, 256>>>(fuse_w, wfuse, 64, 128, 64, tot);
    }
    {
        int tot = 8 * 64 * 9 * 64;
        wt_generic<<<(tot + 255) / 256, 256>>>(rb_w1, wrb1, 64, 64, 64, tot);
        wt_generic<<<(tot + 255) / 256, 256>>>(rb_w2, wrb2, 64, 64, 64, tot);
    }

    sup_kernel<<<(TOPK * BATCH * HW + 255) / 256, 256>>>(S);
    ref_kernel<<<(TOPK * BATCH * NF * HW / 4 + 255) / 256, 256>>>(T);

    convom_kernel<<<dim3(4, 32, 12), 256>>>(x, off_b, mod_b);

    deform_kernel<<<dim3(4, 32, 4), 256, 53248>>>(reg_b);

    conv64_kernel<<<dim3(4, 32, 4), 256, CONV64_SMEM>>>(x, att, 16, 8, wfuse, fuse_b, x, xA, 0);

    float* cur = xA;
    float* nxt = xB;
    for (int r = 0; r < 8; ++r) {
        conv64_kernel<<<dim3(4, 32, 4), 256, CONV64_SMEM>>>(cur, (const float*)0, 8, 8,
                                               wrb1 + r * 36864, rb_b1 + r * 64,
                                               (const float*)0, tmp, 1);
        float* o = (r == 7) ? out : nxt;
        conv64_kernel<<<dim3(4, 32, 4), 256, CONV64_SMEM>>>(tmp, (const float*)0, 8, 8,
                                               wrb2 + r * 36864, rb_b2 + r * 64,
                                               cur, o, 0);
        float* t2 = cur; cur = nxt; nxt = t2;
    }
}

// round 6
// speedup vs baseline: 1.3385x; 1.0306x over previous
#include <cuda_runtime.h>
#include <math.h>

#define H 128
#define W 128
#define HW 16384
#define BATCH 4
#define NF 64
#define TOPK 3

typedef unsigned long long ull;

__device__ __forceinline__ ull pk2(float a, float b) {
    ull r; asm("mov.b64 %0,{%1,%2};" : "=l"(r) : "f"(a), "f"(b)); return r;
}
__device__ __forceinline__ void upk2(ull v, float& a, float& b) {
    asm("mov.b64 {%0,%1},%2;" : "=f"(a), "=f"(b) : "l"(v));
}
__device__ __forceinline__ void ffma2(ull& d, ull a, ull b) {
    asm("fma.rn.f32x2 %0,%1,%2,%0;" : "+l"(d) : "l"(a), "l"(b));
}
__device__ __forceinline__ unsigned smaddr(const void* p) {
    return (unsigned)__cvta_generic_to_shared(p);
}
__device__ __forceinline__ void cp4(unsigned s, const void* g, int pred) {
    asm volatile("{\n\t.reg .pred p;\n\tsetp.ne.u32 p,%2,0;\n\t"
                 "@p cp.async.ca.shared.global [%0],[%1],4;\n\t}"
                 :: "r"(s), "l"(g), "r"(pred));
}
__device__ __forceinline__ void cp16(unsigned s, const void* g, int pred) {
    asm volatile("{\n\t.reg .pred p;\n\tsetp.ne.u32 p,%2,0;\n\t"
                 "@p cp.async.cg.shared.global [%0],[%1],16;\n\t}"
                 :: "r"(s), "l"(g), "r"(pred));
}
__device__ __forceinline__ void cp_commit() { asm volatile("cp.async.commit_group;"); }
template<int N> __device__ __forceinline__ void cp_wait() {
    asm volatile("cp.async.wait_group %0;" :: "n"(N));
}

// ---------------- device global scratch --------------------------------------
static __device__ float g_sup [TOPK*BATCH*HW];
static __device__ float g_ref [TOPK*BATCH*NF*HW];
static __device__ float g_off [TOPK*BATCH*18*HW];
static __device__ float g_mod [TOPK*BATCH*9*HW];
static __device__ float g_att [BATCH*NF*HW];
static __device__ float g_xA  [BATCH*NF*HW];
static __device__ float g_xB  [BATCH*NF*HW];
static __device__ float g_tmp [BATCH*NF*HW];
static __device__ float g_wom [TOPK*128*9*32];
static __device__ float g_wreg[TOPK*64*9*64];
static __device__ float g_wfuse[128*9*64];
static __device__ float g_wrb1[8*64*9*64];
static __device__ float g_wrb2[8*64*9*64];

// ---------------- weight transposes ------------------------------------------
__global__ void wt_generic(const float* __restrict__ src, float* __restrict__ dst,
                           int O, int C, int OP, int total) {
    int idx = blockIdx.x * blockDim.x + threadIdx.x;
    if (idx >= total) return;
    int per = C * 9 * OP;
    int s = idx / per;
    int r = idx - s * per;
    int c = r / (9 * OP);
    int r2 = r - c * (9 * OP);
    int k = r2 / OP;
    int o = r2 - k * OP;
    dst[idx] = (o < O) ? src[((s * O + o) * C + c) * 9 + k] : 0.f;
}

__global__ void wt_om(const float* __restrict__ offw, const float* __restrict__ modw) {
    int idx = blockIdx.x * blockDim.x + threadIdx.x;
    const int total = TOPK * 128 * 9 * 32;
    if (idx >= total) return;
    int i = idx / (128 * 9 * 32);
    int r = idx - i * (128 * 9 * 32);
    int c = r / (9 * 32);
    int r2 = r - c * (9 * 32);
    int k = r2 / 32;
    int o = r2 - k * 32;
    float v = 0.f;
    if (o < 18)      v = offw[((i * 18 + o) * 128 + c) * 9 + k];
    else if (o < 27) v = modw[((i * 9 + (o - 18)) * 128 + c) * 9 + k];
    g_wom[idx] = v;
}

// ---------------- bicubic 2x upsample ----------------------------------------
__global__ void sup_kernel(const float* __restrict__ S) {
    int idx = blockIdx.x * blockDim.x + threadIdx.x;
    if (idx >= TOPK * BATCH * HW) return;
    int ib = idx / HW;
    int p = idx & (HW - 1);
    int oy = p >> 7, ox = p & 127;
    const float* s = S + ib * 64 * 64;
    const float wE0 = -0.03515625f, wE1 = 0.26171875f, wE2 = 0.87890625f, wE3 = -0.10546875f;
    float wy[4], wx[4];
    if (oy & 1) { wy[0] = wE3; wy[1] = wE2; wy[2] = wE1; wy[3] = wE0; }
    else        { wy[0] = wE0; wy[1] = wE1; wy[2] = wE2; wy[3] = wE3; }
    if (ox & 1) { wx[0] = wE3; wx[1] = wE2; wx[2] = wE1; wx[3] = wE0; }
    else        { wx[0] = wE0; wx[1] = wE1; wx[2] = wE2; wx[3] = wE3; }
    int iy0 = (int)floorf(0.5f * (float)oy - 0.25f) - 1;
    int ix0 = (int)floorf(0.5f * (float)ox - 0.25f) - 1;
    float acc = 0.f;
    #pragma unroll
    for (int jy = 0; jy < 4; ++jy) {
        int yy = min(max(iy0 + jy, 0), 63);
        float row = 0.f;
        #pragma unroll
        for (int jx = 0; jx < 4; ++jx) {
            int xx = min(max(ix0 + jx, 0), 63);
            row += wx[jx] * s[yy * 64 + xx];
        }
        acc += wy[jy] * row;
    }
    g_sup[idx] = acc;
}

// ---------------- ref = T * broadcast(S_up) ----------------------------------
__global__ void ref_kernel(const float* __restrict__ T) {
    int idx = blockIdx.x * blockDim.x + threadIdx.x;
    const int total = TOPK * BATCH * NF * HW / 4;
    if (idx >= total) return;
    int q = idx & 4095;
    int ibc = idx >> 12;
    int ib = ibc / NF;
    float4 t = ((const float4*)T)[idx];
    float4 s = ((const float4*)g_sup)[ib * 4096 + q];
    float4 r;
    r.x = t.x * s.x; r.y = t.y * s.y; r.z = t.z * s.z; r.w = t.w * s.w;
    ((float4*)g_ref)[idx] = r;
}

// ---------------- offset/modulator conv (pipelined) --------------------------
__global__ void __launch_bounds__(256) convom_kernel(const float* __restrict__ x,
                                                     const float* __restrict__ off_b,
                                                     const float* __restrict__ mod_b) {
    __shared__ float patchB[2][1632];
    __shared__ __align__(16) float wsmB[2][2304];
    int tid = threadIdx.x;
    int bx = blockIdx.x, by = blockIdx.y, z = blockIdx.z;
    int i = z >> 2, b = z & 3;
    const float* inA = x + b * NF * HW;
    const float* inB = g_ref + (i * BATCH + b) * NF * HW;
    const float* wT = g_wom + i * (128 * 9 * 32);
    int g = tid >> 5, col = tid & 31;
    ull acc[4][2];
    #pragma unroll
    for (int a = 0; a < 4; ++a) { acc[a][0] = 0ull; acc[a][1] = 0ull; }

    int fgo[7], fso[7], fcp[7]; int fva[7];
    #pragma unroll
    for (int f = 0; f < 7; ++f) {
        int idx = tid + f * 256;
        int c = idx / 204;
        int rr = idx - c * 204;
        int r = rr / 34;
        int cl = rr - r * 34;
        int y = by * 4 + r - 1, xx = bx * 32 + cl - 1;
        fcp[f] = (c & 7) * HW;
        fgo[f] = y * 128 + xx;
        fso[f] = idx;
        fva[f] = (idx < 1632) && ((unsigned)y < 128u) && ((unsigned)xx < 128u);
    }

    for (int idx = tid; idx < 1632; idx += 256) { patchB[0][idx] = 0.f; patchB[1][idx] = 0.f; }
    __syncthreads();

    {
        const float* bp = inA;
        #pragma unroll
        for (int f = 0; f < 7; ++f)
            cp4(smaddr(&patchB[0][0]) + fso[f] * 4, bp + fcp[f] + fgo[f], fva[f]);
        #pragma unroll
        for (int f = 0; f < 3; ++f) {
            int idx = tid + f * 256;
            cp16(smaddr(&wsmB[0][0]) + idx * 16, wT + idx * 4, (f < 2) || (tid < 64));
        }
        cp_commit();
    }

    for (int chunk = 0; chunk < 16; ++chunk) {
        int cur = chunk & 1;
        if (chunk + 1 < 16) {
            int nxt = cur ^ 1;
            int nc = chunk + 1;
            const float* bp = (nc < 8) ? (inA + nc * 8 * HW) : (inB + (nc - 8) * 8 * HW);
            #pragma unroll
            for (int f = 0; f < 7; ++f)
                cp4(smaddr(&patchB[nxt][0]) + fso[f] * 4, bp + fcp[f] + fgo[f], fva[f]);
            const float* wc = wT + nc * 2304;
            #pragma unroll
            for (int f = 0; f < 3; ++f) {
                int idx = tid + f * 256;
                cp16(smaddr(&wsmB[nxt][0]) + idx * 16, wc + idx * 4, (f < 2) || (tid < 64));
            }
            cp_commit();
            cp_wait<1>();
        } else {
            cp_wait<0>();
        }
        __syncthreads();
        const float* patch = patchB[cur];
        const float* wsm = wsmB[cur];
        #pragma unroll
        for (int c = 0; c < 8; ++c) {
            #pragma unroll
            for (int k = 0; k < 9; ++k) {
                const int ky = k / 3, kx = k - ky * 3;
                ulonglong2 wv = *(const ulonglong2*)&wsm[(c * 9 + k) * 32 + (g << 2)];
                #pragma unroll
                for (int ry = 0; ry < 4; ++ry) {
                    float iv = patch[(c * 6 + ry + ky) * 34 + col + kx];
                    ull iv2 = pk2(iv, iv);
                    ffma2(acc[ry][0], iv2, wv.x);
                    ffma2(acc[ry][1], iv2, wv.y);
                }
            }
        }
        __syncthreads();
    }
    int oc0 = g << 2;
    int x0 = bx * 32 + col;
    #pragma unroll
    for (int pj = 0; pj < 2; ++pj) {
        #pragma unroll
        for (int ry = 0; ry < 4; ++ry) {
            float v0, v1;
            upk2(acc[ry][pj], v0, v1);
            float vv[2] = {v0, v1};
            #pragma unroll
            for (int h = 0; h < 2; ++h) {
                int oc = oc0 + pj * 2 + h;
                if (oc < 18) {
                    float v = vv[h] + off_b[i * 18 + oc];
                    v = fminf(fmaxf(v, -32.f), 32.f);
                    g_off[((i * BATCH + b) * 18 + oc) * HW + (by * 4 + ry) * 128 + x0] = v;
                } else if (oc < 27) {
                    float t = vv[h] + mod_b[i * 9 + (oc - 18)];
                    g_mod[((i * BATCH + b) * 9 + (oc - 18)) * HW + (by * 4 + ry) * 128 + x0]
                        = 2.f / (1.f + expf(-t));
                }
            }
        }
    }
}

// ---------------- generic conv3x3 Cout=64 (pipelined) ------------------------
__global__ void __launch_bounds__(256) conv64_kernel(const float* __restrict__ inA,
                                                     const float* __restrict__ inB,
                                                     int nChunks, int kSplit,
                                                     const float* __restrict__ wT,
                                                     const float* __restrict__ bias,
                                                     const float* __restrict__ resid,
                                                     float* __restrict__ out,
                                                     int doRelu) {
    extern __shared__ __align__(16) float dynsm[];
    float* patchB0 = dynsm;
    float* patchB1 = dynsm + 1632;
    float* wsmB0   = dynsm + 3264;
    float* wsmB1   = dynsm + 7872;
    int tid = threadIdx.x;
    int bx = blockIdx.x, by = blockIdx.y, b = blockIdx.z;
    const float* inAb = inA + b * NF * HW;
    const float* inBb = inB ? (inB + b * NF * HW) : (const float*)0;
    int g = tid >> 5, col = tid & 31;
    ull acc[4][4];
    #pragma unroll
    for (int a = 0; a < 4; ++a)
        #pragma unroll
        for (int o = 0; o < 4; ++o) acc[a][o] = 0ull;

    int fgo[7], fso[7], fcp[7]; int fva[7];
    #pragma unroll
    for (int f = 0; f < 7; ++f) {
        int idx = tid + f * 256;
        int c = idx / 204;
        int rr = idx - c * 204;
        int r = rr / 34;
        int cl = rr - r * 34;
        int y = by * 4 + r - 1, xx = bx * 32 + cl - 1;
        fcp[f] = (c & 7) * HW;
        fgo[f] = y * 128 + xx;
        fso[f] = idx;
        fva[f] = (idx < 1632) && ((unsigned)y < 128u) && ((unsigned)xx < 128u);
    }

    for (int idx = tid; idx < 1632; idx += 256) { patchB0[idx] = 0.f; patchB1[idx] = 0.f; }
    __syncthreads();

    {
        const float* bp = (0 < kSplit) ? inAb : inBb;
        #pragma unroll
        for (int f = 0; f < 7; ++f)
            cp4(smaddr(patchB0) + fso[f] * 4, bp + fcp[f] + fgo[f], fva[f]);
        #pragma unroll
        for (int f = 0; f < 5; ++f) {
            int idx = tid + f * 256;
            cp16(smaddr(wsmB0) + idx * 16, wT + idx * 4, (f < 4) || (tid < 128));
        }
        cp_commit();
    }

    for (int chunk = 0; chunk < nChunks; ++chunk) {
        int cur = chunk & 1;
        if (chunk + 1 < nChunks) {
            int nc = chunk + 1;
            float* pb = (cur == 0) ? patchB1 : patchB0;
            float* wb = (cur == 0) ? wsmB1 : wsmB0;
            const float* bp = (nc < kSplit) ? (inAb + nc * 8 * HW)
                                            : (inBb + (nc - kSplit) * 8 * HW);
            #pragma unroll
            for (int f = 0; f < 7; ++f)
                cp4(smaddr(pb) + fso[f] * 4, bp + fcp[f] + fgo[f], fva[f]);
            const float* wc = wT + nc * 4608;
            #pragma unroll
            for (int f = 0; f < 5; ++f) {
                int idx = tid + f * 256;
                cp16(smaddr(wb) + idx * 16, wc + idx * 4, (f < 4) || (tid < 128));
            }
            cp_commit();
            cp_wait<1>();
        } else {
            cp_wait<0>();
        }
        __syncthreads();
        const float* patch = (cur == 0) ? patchB0 : patchB1;
        const float* wsm = (cur == 0) ? wsmB0 : wsmB1;
        #pragma unroll
        for (int c = 0; c < 8; ++c) {
            #pragma unroll
            for (int k = 0; k < 9; ++k) {
                const int ky = k / 3, kx = k - ky * 3;
                const ulonglong2* wp = (const ulonglong2*)&wsm[(c * 9 + k) * 64 + (g << 3)];
                ulonglong2 wa = wp[0];
                ulonglong2 wb2 = wp[1];
                #pragma unroll
                for (int ry = 0; ry < 4; ++ry) {
                    float iv = patch[(c * 6 + ry + ky) * 34 + col + kx];
                    ull iv2 = pk2(iv, iv);
                    ffma2(acc[ry][0], iv2, wa.x);
                    ffma2(acc[ry][1], iv2, wa.y);
                    ffma2(acc[ry][2], iv2, wb2.x);
                    ffma2(acc[ry][3], iv2, wb2.y);
                }
            }
        }
        __syncthreads();
    }
    int oc0 = g << 3;
    int x0 = bx * 32 + col;
    #pragma unroll
    for (int pj = 0; pj < 4; ++pj) {
        #pragma unroll
        for (int ry = 0; ry < 4; ++ry) {
            float v0, v1;
            upk2(acc[ry][pj], v0, v1);
            float vv[2] = {v0, v1};
            #pragma unroll
            for (int h = 0; h < 2; ++h) {
                int oc = oc0 + pj * 2 + h;
                float v = vv[h] + bias[oc];
                if (doRelu) v = fmaxf(v, 0.f);
                int oidx = (b * NF + oc) * HW + (by * 4 + ry) * 128 + x0;
                if (resid) v += resid[oidx];
                out[oidx] = v;
            }
        }
    }
}

// ---------------- deformable conv (register coefs + async weights) -----------
__global__ void __launch_bounds__(256) deform_kernel(const float* __restrict__ reg_b) {
    extern __shared__ __align__(16) float sm[];
    float* samp = sm;               // 64 x 128 = 8192 floats
    float* wsmB0 = sm + 8192;       // 4096 floats
    float* wsmB1 = sm + 12288;      // 4096 floats
    int tid = threadIdx.x;
    int bx = blockIdx.x, by = blockIdx.y, b = blockIdx.z;
    int g = tid >> 5, col = tid & 31;
    ull acc[4][4];
    #pragma unroll
    for (int a = 0; a < 4; ++a)
        #pragma unroll
        for (int o = 0; o < 4; ++o) acc[a][o] = 0ull;
    int p = tid & 127;
    int chalf = tid >> 7;
    int py_ = by * 4 + (p >> 5);
    int px_ = bx * 32 + (p & 31);
    int po = py_ * 128 + px_;

    // weight cp descriptors: 1024 cp16 per iter, 4 per thread
    // idx = tid + f*256; c = idx>>4; q = idx&15; elem offset q*4 within 64-float row
    // prologue: weights for iter 0 (i=0, kk=0)
    {
        const float* wb = g_wreg;
        #pragma unroll
        for (int f = 0; f < 4; ++f) {
            int idx = tid + f * 256;
            int c = idx >> 4, q = idx & 15;
            cp16(smaddr(wsmB0) + idx * 16, wb + (c * 9 + 0) * 64 + q * 4, 1);
        }
        cp_commit();
    }

    for (int it = 0; it < 27; ++it) {
        int i = it / 9, kk = it - i * 9;
        const float* refb = g_ref + (i * BATCH + b) * NF * HW;
        const float* offb = g_off + (i * BATCH + b) * 18 * HW;
        const float* modb = g_mod + (i * BATCH + b) * 9 * HW;

        // coefs in registers (all threads compute their pixel's coefs)
        float dy = offb[(2 * kk) * HW + po];
        float dx = offb[(2 * kk + 1) * HW + po];
        float m  = modb[kk * HW + po];
        float py = (float)(py_ + kk / 3 - 1) + dy;
        float px = (float)(px_ + kk % 3 - 1) + dx;
        float fy = floorf(py), fx = floorf(px);
        float ty = py - fy, tx = px - fx;
        int iy0 = (int)fy, ix0 = (int)fx;
        int iy1 = iy0 + 1, ix1 = ix0 + 1;
        float vy0 = ((unsigned)iy0 < 128u) ? 1.f : 0.f;
        float vy1 = ((unsigned)iy1 < 128u) ? 1.f : 0.f;
        float vx0 = ((unsigned)ix0 < 128u) ? 1.f : 0.f;
        float vx1 = ((unsigned)ix1 < 128u) ? 1.f : 0.f;
        float f00 = (1.f - ty) * (1.f - tx) * m * vy0 * vx0;
        float f01 = (1.f - ty) * tx * m * vy0 * vx1;
        float f10 = ty * (1.f - tx) * m * vy1 * vx0;
        float f11 = ty * tx * m * vy1 * vx1;
        int r0 = min(max(iy0, 0), 127) * 128;
        int r1 = min(max(iy1, 0), 127) * 128;
        int c0 = min(max(ix0, 0), 127);
        int c1 = min(max(ix1, 0), 127);

        __syncthreads();   // previous FMA done reading samp
        {
            const float* rbase = refb + chalf * 32 * HW;
            #pragma unroll 4
            for (int j = 0; j < 32; ++j) {
                const float* rc = rbase + j * HW;
                float v = f00 * rc[r0 + c0] + f01 * rc[r0 + c1] +
                          f10 * rc[r1 + c0] + f11 * rc[r1 + c1];
                samp[(chalf * 32 + j) * 128 + p] = v;
            }
        }
        // issue next iter's weights into the other buffer
        float* wcur = (it & 1) ? wsmB1 : wsmB0;
        if (it + 1 < 27) {
            int nit = it + 1;
            int ni = nit / 9, nkk = nit - ni * 9;
            const float* wb = g_wreg + ni * (64 * 9 * 64);
            float* wnxt = (it & 1) ? wsmB0 : wsmB1;
            #pragma unroll
            for (int f = 0; f < 4; ++f) {
                int idx = tid + f * 256;
                int c = idx >> 4, q = idx & 15;
                cp16(smaddr(wnxt) + idx * 16, wb + (c * 9 + nkk) * 64 + q * 4, 1);
            }
            cp_commit();
            cp_wait<1>();
        } else {
            cp_wait<0>();
        }
        __syncthreads();   // samp + weights ready
        #pragma unroll 4
        for (int c = 0; c < 64; ++c) {
            const ulonglong2* wp = (const ulonglong2*)(wcur + c * 64 + (g << 3));
            ulonglong2 wa = wp[0];
            ulonglong2 wb2 = wp[1];
            float sv0 = samp[c * 128 + col];
            float sv1 = samp[c * 128 + 32 + col];
            float sv2 = samp[c * 128 + 64 + col];
            float sv3 = samp[c * 128 + 96 + col];
            ull s0 = pk2(sv0, sv0), s1 = pk2(sv1, sv1);
            ull s2 = pk2(sv2, sv2), s3 = pk2(sv3, sv3);
            ffma2(acc[0][0], s0, wa.x); ffma2(acc[0][1], s0, wa.y);
            ffma2(acc[0][2], s0, wb2.x); ffma2(acc[0][3], s0, wb2.y);
            ffma2(acc[1][0], s1, wa.x); ffma2(acc[1][1], s1, wa.y);
            ffma2(acc[1][2], s1, wb2.x); ffma2(acc[1][3], s1, wb2.y);
            ffma2(acc[2][0], s2, wa.x); ffma2(acc[2][1], s2, wa.y);
            ffma2(acc[2][2], s2, wb2.x); ffma2(acc[2][3], s2, wb2.y);
            ffma2(acc[3][0], s3, wa.x); ffma2(acc[3][1], s3, wa.y);
            ffma2(acc[3][2], s3, wb2.x); ffma2(acc[3][3], s3, wb2.y);
        }
    }
    __syncthreads();
    int oc0 = g << 3;
    int x0 = bx * 32 + col;
    #pragma unroll
    for (int pj = 0; pj < 4; ++pj) {
        #pragma unroll
        for (int ry = 0; ry < 4; ++ry) {
            float v0, v1;
            upk2(acc[ry][pj], v0, v1);
            float vv[2] = {v0, v1};
            #pragma unroll
            for (int h = 0; h < 2; ++h) {
                int oc = oc0 + pj * 2 + h;
                float bs = reg_b[oc] + reg_b[64 + oc] + reg_b[128 + oc];
                g_att[(b * NF + oc) * HW + (by * 4 + ry) * 128 + x0] = vv[h] + bs;
            }
        }
    }
}

// ---------------- host launcher ----------------------------------------------
extern "C" void kernel_launch(void* const* d_in, const int* in_sizes, int n_in,
                              void* d_out, int out_size) {
    (void)in_sizes; (void)n_in; (void)out_size;
    const float* x      = (const float*)d_in[0];
    const float* T      = (const float*)d_in[1];
    const float* S      = (const float*)d_in[2];
    const float* off_w  = (const float*)d_in[3];
    const float* off_b  = (const float*)d_in[4];
    const float* mod_w  = (const float*)d_in[5];
    const float* mod_b  = (const float*)d_in[6];
    const float* reg_w  = (const float*)d_in[7];
    const float* reg_b  = (const float*)d_in[8];
    const float* fuse_w = (const float*)d_in[9];
    const float* fuse_b = (const float*)d_in[10];
    const float* rb_w1  = (const float*)d_in[11];
    const float* rb_b1  = (const float*)d_in[12];
    const float* rb_w2  = (const float*)d_in[13];
    const float* rb_b2  = (const float*)d_in[14];
    float* out = (float*)d_out;

    const int CONV64_SMEM = (2 * 1632 + 2 * 4608) * 4;   // 49920 B
    const int DEFORM_SMEM = (8192 + 2 * 4096) * 4;       // 65536 B
    cudaFuncSetAttribute(conv64_kernel, cudaFuncAttributeMaxDynamicSharedMemorySize, CONV64_SMEM);
    cudaFuncSetAttribute(deform_kernel, cudaFuncAttributeMaxDynamicSharedMemorySize, DEFORM_SMEM);

    float *wreg, *wfuse, *wrb1, *wrb2, *xA, *xB, *tmp, *att;
    cudaGetSymbolAddress((void**)&wreg,  g_wreg);
    cudaGetSymbolAddress((void**)&wfuse, g_wfuse);
    cudaGetSymbolAddress((void**)&wrb1,  g_wrb1);
    cudaGetSymbolAddress((void**)&wrb2,  g_wrb2);
    cudaGetSymbolAddress((void**)&xA,    g_xA);
    cudaGetSymbolAddress((void**)&xB,    g_xB);
    cudaGetSymbolAddress((void**)&tmp,   g_tmp);
    cudaGetSymbolAddress((void**)&att,   g_att);

    // launch order chosen so deform_kernel is launch index 5 (ncu -s 5 -c 1)
    sup_kernel<<<(TOPK * BATCH * HW + 255) / 256, 256>>>(S);                       // 0
    ref_kernel<<<(TOPK * BATCH * NF * HW / 4 + 255) / 256, 256>>>(T);              // 1
    {
        int tot = TOPK * 128 * 9 * 32;
        wt_om<<<(tot + 255) / 256, 256>>>(off_w, mod_w);                           // 2
    }
    {
        int tot = TOPK * 64 * 9 * 64;
        wt_generic<<<(tot + 255) / 256, 256>>>(reg_w, wreg, 64, 64, 64, tot);      // 3
    }
    convom_kernel<<<dim3(4, 32, 12), 256>>>(x, off_b, mod_b);                      // 4
    deform_kernel<<<dim3(4, 32, 4), 256, DEFORM_SMEM>>>(reg_b);                    // 5 <- profiled
    {
        int tot = 128 * 9 * 64;
        wt_generic<<<(tot + 255) / 256, 256>>>(fuse_w, wfuse, 64, 128, 64, tot);   // 6
    }
    {
        int tot = 8 * 64 * 9 * 64;
        wt_generic<<<(tot + 255) / 256, 256>>>(rb_w1, wrb1, 64, 64, 64, tot);      // 7
        wt_generic<<<(tot + 255) / 256, 256>>>(rb_w2, wrb2, 64, 64, 64, tot);      // 8
    }

    conv64_kernel<<<dim3(4, 32, 4), 256, CONV64_SMEM>>>(x, att, 16, 8, wfuse, fuse_b, x, xA, 0);

    float* cur = xA;
    float* nxt = xB;
    for (int r = 0; r < 8; ++r) {
        conv64_kernel<<<dim3(4, 32, 4), 256, CONV64_SMEM>>>(cur, (const float*)0, 8, 8,
                                               wrb1 + r * 36864, rb_b1 + r * 64,
                                               (const float*)0, tmp, 1);
        float* o = (r == 7) ? out : nxt;
        conv64_kernel<<<dim3(4, 32, 4), 256, CONV64_SMEM>>>(tmp, (const float*)0, 8, 8,
                                               wrb2 + r * 36864, rb_b2 + r * 64,
                                               cur, o, 0);
        float* t2 = cur; cur = nxt; nxt = t2;
    }
}